// round 14
// baseline (speedup 1.0000x reference)
#include <cuda_runtime.h>
#include <math.h>

#define SS 64
#define WW 128
#define DD 256
#define HWW 256
#define NC 13

// ---------------- scratch ----------------
__device__ float g_gi[2 * WW * SS * 768];      // [d][w][s][768]
__device__ float g_wordenc[SS * WW * 512];     // [s*128+w][512]
__device__ float g_sentsumm[SS * 512];         // [s][512]
__device__ float g_gis[2 * SS * 1536];         // [d][s][1536]
__device__ float g_sentenc[SS * 1024];         // [s][1024]
__device__ float g_usent[SS * 1024];           // [s][1024]
__device__ float g_sink;

__device__ __forceinline__ float fsig(float x) {
    return __fdividef(1.0f, 1.0f + __expf(-x));
}
__device__ __forceinline__ float ftanh(float x) {
    return 1.0f - __fdividef(2.0f, __expf(2.0f * x) + 1.0f);
}

__device__ __forceinline__ unsigned long long ffma2(unsigned long long a,
                                                    unsigned long long b,
                                                    unsigned long long c) {
    unsigned long long d;
    asm("fma.rn.f32x2 %0, %1, %2, %3;" : "=l"(d) : "l"(a), "l"(b), "l"(c));
    return d;
}

__device__ __forceinline__ unsigned smem_u32(const void* p) {
    unsigned a;
    asm("{ .reg .u64 t; cvta.to.shared.u64 t, %1; cvt.u32.u64 %0, t; }" : "=r"(a) : "l"(p));
    return a;
}

// 4-byte async copy: global -> (transposed) shared, no register staging
__device__ __forceinline__ void cpa4(unsigned dst, const float* src) {
    asm volatile("cp.async.ca.shared.global [%0], [%1], 4;" :: "r"(dst), "l"(src));
}
#define CP_COMMIT() asm volatile("cp.async.commit_group;" ::: "memory")
#define CP_WAIT0()  asm volatile("cp.async.wait_group 0;" ::: "memory")

// cluster-scope acquire wait on mbarrier phase parity
__device__ __forceinline__ void mbar_wait_cluster(unsigned mbar, unsigned parity) {
    asm volatile(
        "{\n\t.reg .pred P1;\n\t"
        "WAIT_LOOP_%=:\n\t"
        "mbarrier.try_wait.parity.acquire.cluster.shared::cta.b64 P1, [%0], %1, 0x989680;\n\t"
        "@P1 bra.uni WAIT_DONE_%=;\n\t"
        "bra.uni WAIT_LOOP_%=;\n\t"
        "WAIT_DONE_%=:\n\t}"
        :: "r"(mbar), "r"(parity) : "memory");
}

// ---------------- init ----------------
__global__ void k_init(float* __restrict__ out) {
    int i = blockIdx.x * blockDim.x + threadIdx.x;
    if (i < 8256) out[i] = 1.0f;   // word_w + sent_w are softmax over size-1 axis -> ones
}

// ---------------- K1: gi[d][m][n] = emb[doc[m]] @ wWi[d]^T + wbi[d],  m = w*64+s -------
// 128x128 tile, 8x8/thread, cp.async 2-stage double buffer (transposed smem fill).
__global__ void __launch_bounds__(256) k_gi(const int* __restrict__ doc,
                                            const float* __restrict__ emb,
                                            const float* __restrict__ wWi,
                                            const float* __restrict__ wbi) {
    int n0 = blockIdx.x * 128, mt = blockIdx.y, d = blockIdx.z;
    __shared__ float As[2][16 * 132];
    __shared__ float Bs[2][16 * 132];
    __shared__ int toks[128];
    int tid = threadIdx.x;
    if (tid < 128) {
        int m = mt * 128 + tid;                  // w = m>>6, s = m&63
        toks[tid] = doc[(m & 63) * WW + (m >> 6)];
    }
    __syncthreads();
    int tx = tid & 15, ty = tid >> 4;
    int lrow = tid >> 1, kk0 = (tid & 1) * 8;
    const float* arow = emb + (long)toks[lrow] * DD + kk0;
    const float* brow = wWi + (d * 768 + n0 + lrow) * 256 + kk0;
    unsigned sa = smem_u32(&As[0][0]);
    unsigned sb = smem_u32(&Bs[0][0]);
    unsigned soff = (unsigned)((kk0 * 132 + lrow) * 4);   // dst of u=0 in buf 0

    // prologue: fill chunk 0 into buf 0
#pragma unroll
    for (int u = 0; u < 8; u++) {
        cpa4(sa + soff + (unsigned)(u * 132 * 4), arow + u);
        cpa4(sb + soff + (unsigned)(u * 132 * 4), brow + u);
    }
    CP_COMMIT();

    float acc[8][8] = {};
    for (int ch = 0; ch < 16; ch++) {
        CP_WAIT0();
        __syncthreads();
        if (ch + 1 < 16) {                       // fill next chunk, overlapped with compute
            unsigned db = (unsigned)(((ch + 1) & 1) * 16 * 132 * 4);
            int kc = (ch + 1) * 16;
#pragma unroll
            for (int u = 0; u < 8; u++) {
                cpa4(sa + db + soff + (unsigned)(u * 132 * 4), arow + kc + u);
                cpa4(sb + db + soff + (unsigned)(u * 132 * 4), brow + kc + u);
            }
            CP_COMMIT();
        }
        const float* Ab = As[ch & 1];
        const float* Bb = Bs[ch & 1];
#pragma unroll
        for (int kk = 0; kk < 16; kk++) {
            float4 x0 = *(const float4*)&Ab[kk * 132 + ty * 8];
            float4 x1 = *(const float4*)&Ab[kk * 132 + ty * 8 + 4];
            float4 y0 = *(const float4*)&Bb[kk * 132 + tx * 8];
            float4 y1 = *(const float4*)&Bb[kk * 132 + tx * 8 + 4];
            float av[8] = {x0.x, x0.y, x0.z, x0.w, x1.x, x1.y, x1.z, x1.w};
            float bv[8] = {y0.x, y0.y, y0.z, y0.w, y1.x, y1.y, y1.z, y1.w};
#pragma unroll
            for (int i = 0; i < 8; i++)
#pragma unroll
                for (int j = 0; j < 8; j++) acc[i][j] += av[i] * bv[j];
        }
        __syncthreads();
    }
    float4 c0 = *(const float4*)&wbi[d * 768 + n0 + tx * 8];
    float4 c1 = *(const float4*)&wbi[d * 768 + n0 + tx * 8 + 4];
    float bb[8] = {c0.x, c0.y, c0.z, c0.w, c1.x, c1.y, c1.z, c1.w};
#pragma unroll
    for (int i = 0; i < 8; i++) {
        int m = mt * 128 + ty * 8 + i;
        float* dst = g_gi + ((long)d * 8192 + m) * 768 + n0 + tx * 8;
        float4 v0 = make_float4(acc[i][0] + bb[0], acc[i][1] + bb[1],
                                acc[i][2] + bb[2], acc[i][3] + bb[3]);
        float4 v1 = make_float4(acc[i][4] + bb[4], acc[i][5] + bb[5],
                                acc[i][6] + bb[6], acc[i][7] + bb[7]);
        *(float4*)dst = v0;
        *(float4*)(dst + 4) = v1;
    }
}

// ---------------- K2: persistent word-GRU recurrence (unchanged from R13, passing) -------
__global__ void __launch_bounds__(256, 1) __cluster_dims__(8, 1, 1)
k_recur(const float* __restrict__ wWh, const float* __restrict__ wbh) {
    __shared__ __align__(16) float h_sm[2][2][4 * 264];     // [group][buf][4 rows]
    __shared__ __align__(8) unsigned long long mbars[2][2]; // [group][buf]
    int c = blockIdx.x;
    int d = c >> 6, sb = (c >> 3) & 7, jb = c & 7;
    int tid = threadIdx.x;
    int warp = tid >> 5, lane = tid & 31;
    int jq = lane >> 3, ks = lane & 7;
    int ks3 = ks & 3, hs = ks >> 2;
    int jg = jb * 32 + warp * 4 + jq;
    int sb8 = sb * 8;
    int kbase = ks3 * 64 + hs * 4;

    unsigned long long whr2[3][16];
#pragma unroll
    for (int g = 0; g < 3; g++) {
        const float* wr = wWh + (d * 768 + g * 256 + jg) * 256;
#pragma unroll
        for (int t = 0; t < 8; t++) {
            whr2[g][2 * t]     = *(const unsigned long long*)(wr + kbase + 8 * t);
            whr2[g][2 * t + 1] = *(const unsigned long long*)(wr + kbase + 8 * t + 2);
        }
    }
    float bhr = wbh[d * 768 + jg];
    float bhz = wbh[d * 768 + 256 + jg];
    float bhn = wbh[d * 768 + 512 + jg];

    for (int i = tid; i < 4 * 264; i += 256) {
        h_sm[0][0][i] = 0.0f;
        h_sm[1][0][i] = 0.0f;
    }
    int hoff[4];
#pragma unroll
    for (int i = 0; i < 4; i++) hoff[i] = (i ^ ks3) * 264;

    unsigned hbase = smem_u32(&h_sm[0][0][0]);
    unsigned mbase = smem_u32(&mbars[0][0]);
    unsigned dmb = mbase - hbase;
    unsigned pa[8];
#pragma unroll
    for (int r = 0; r < 8; r++) {
        unsigned peer;
        asm("mapa.shared::cluster.u32 %0, %1, %2;" : "=r"(peer) : "r"(hbase), "r"(r));
        pa[r] = peer;
    }

    if (tid == 0) {
#pragma unroll
        for (int g = 0; g < 2; g++)
#pragma unroll
            for (int b = 0; b < 2; b++)
                asm volatile("mbarrier.init.shared.b64 [%0], 1;"
                             :: "r"(mbase + (unsigned)((g * 2 + b) * 8)) : "memory");
    }
    asm volatile("barrier.cluster.arrive.aligned;" ::: "memory");
    asm volatile("barrier.cluster.wait.aligned;" ::: "memory");

    const float* gib = g_gi + ((d * WW) * SS + (sb8 + ks)) * 768 + jg;
    float gi0 = __ldg(gib), gi1 = __ldg(gib + 256), gi2 = __ldg(gib + 512);

    for (int w = 0; w < WW; w++) {
        int b = w & 1, bn = b ^ 1;
        unsigned parity = ((unsigned)(w >> 1) + 1u - (unsigned)b) & 1u;

        if (tid == 0 && w + 1 < WW) {
            asm volatile("mbarrier.arrive.expect_tx.shared::cta.b64 _, [%0], %1;"
                         :: "r"(mbase + (unsigned)(bn * 8)), "r"(4096u) : "memory");
            asm volatile("mbarrier.arrive.expect_tx.shared::cta.b64 _, [%0], %1;"
                         :: "r"(mbase + (unsigned)((2 + bn) * 8)), "r"(4096u) : "memory");
        }

#pragma unroll
        for (int g = 0; g < 2; g++) {
            if (w > 0) mbar_wait_cluster(mbase + (unsigned)((g * 2 + b) * 8), parity);
            const float* hp = &h_sm[g][b][0];

            unsigned long long acc2[3][4];
#pragma unroll
            for (int gg = 0; gg < 3; gg++)
#pragma unroll
                for (int i = 0; i < 4; i++) acc2[gg][i] = 0ull;
#pragma unroll
            for (int t = 0; t < 8; t++) {
#pragma unroll
                for (int i = 0; i < 4; i++) {
                    ulonglong2 hv = *(const ulonglong2*)(hp + hoff[i] + kbase + 8 * t);
#pragma unroll
                    for (int gg = 0; gg < 3; gg++) {
                        acc2[gg][i] = ffma2(hv.x, whr2[gg][2 * t], acc2[gg][i]);
                        acc2[gg][i] = ffma2(hv.y, whr2[gg][2 * t + 1], acc2[gg][i]);
                    }
                }
            }
            float a0[4], a1[4], a2[4];
#pragma unroll
            for (int i = 0; i < 4; i++) {
                float2 f0 = *(float2*)&acc2[0][i]; a0[i] = f0.x + f0.y;
                float2 f1 = *(float2*)&acc2[1][i]; a1[i] = f1.x + f1.y;
                float2 f2 = *(float2*)&acc2[2][i]; a2[i] = f2.x + f2.y;
            }
#pragma unroll
            for (int i = 0; i < 4; i++) {
                a0[i] += __shfl_xor_sync(0xffffffffu, a0[i], 4, 8);
                a1[i] += __shfl_xor_sync(0xffffffffu, a1[i], 4, 8);
                a2[i] += __shfl_xor_sync(0xffffffffu, a2[i], 4, 8);
            }
#pragma unroll
            for (int i = 0; i < 2; i++) {
                a0[i] += __shfl_xor_sync(0xffffffffu, a0[i ^ 2], 2, 8);
                a1[i] += __shfl_xor_sync(0xffffffffu, a1[i ^ 2], 2, 8);
                a2[i] += __shfl_xor_sync(0xffffffffu, a2[i ^ 2], 2, 8);
            }
            a0[0] += __shfl_xor_sync(0xffffffffu, a0[1], 1, 8);
            a1[0] += __shfl_xor_sync(0xffffffffu, a1[1], 1, 8);
            a2[0] += __shfl_xor_sync(0xffffffffu, a2[1], 1, 8);

            if (hs == g) {
                float h_old = hp[ks3 * 264 + jg];
                float r = fsig(gi0 + a0[0] + bhr);
                float z = fsig(gi1 + a1[0] + bhz);
                float n = ftanh(gi2 + r * (a2[0] + bhn));
                float hn = (1.0f - z) * n + z * h_old;

                if (w + 1 < WW) {
                    unsigned off = (unsigned)(((g * 2 + bn) * (4 * 264) + ks3 * 264 + jg) * 4);
                    unsigned mboff = dmb + (unsigned)((g * 2 + bn) * 8);
                    unsigned uv = __float_as_uint(hn);
#pragma unroll
                    for (int r8 = 0; r8 < 8; r8++) {
                        asm volatile(
                            "st.async.shared::cluster.mbarrier::complete_tx::bytes.b32 [%0], %1, [%2];"
                            :: "r"(pa[r8] + off), "r"(uv), "r"(pa[r8] + mboff) : "memory");
                    }
                }
                g_wordenc[((sb8 + ks) * WW + w) * 512 + d * 256 + jg] = hn;
                if (w + 1 < WW) {
                    const float* gn = gib + (w + 1) * (SS * 768);
                    gi0 = __ldg(gn); gi1 = __ldg(gn + 256); gi2 = __ldg(gn + 512);
                }
            }
        }
    }
    asm volatile("barrier.cluster.arrive.aligned;" ::: "memory");
    asm volatile("barrier.cluster.wait.aligned;" ::: "memory");
}

// ---------------- K3: u_word GEMM + fused per-sentence reduction (cp.async pipeline) -----
__global__ void __launch_bounds__(256) k_uword(const float* __restrict__ waW,
                                               const float* __restrict__ wab) {
    int n0 = blockIdx.x * 128, mt = blockIdx.y;
    __shared__ float As[2][16 * 132];
    __shared__ float Bs[2][16 * 132];
    int tid = threadIdx.x;
    int tx = tid & 15, ty = tid >> 4;
    int lrow = tid >> 1, kk0 = (tid & 1) * 8;
    const float* arow = g_wordenc + (mt * 128 + lrow) * 512 + kk0;
    const float* brow = waW + (n0 + lrow) * 512 + kk0;
    unsigned sa = smem_u32(&As[0][0]);
    unsigned sb = smem_u32(&Bs[0][0]);
    unsigned soff = (unsigned)((kk0 * 132 + lrow) * 4);

#pragma unroll
    for (int u = 0; u < 8; u++) {
        cpa4(sa + soff + (unsigned)(u * 132 * 4), arow + u);
        cpa4(sb + soff + (unsigned)(u * 132 * 4), brow + u);
    }
    CP_COMMIT();

    float acc[8][8] = {};
    for (int ch = 0; ch < 32; ch++) {
        CP_WAIT0();
        __syncthreads();
        if (ch + 1 < 32) {
            unsigned db = (unsigned)(((ch + 1) & 1) * 16 * 132 * 4);
            int kc = (ch + 1) * 16;
#pragma unroll
            for (int u = 0; u < 8; u++) {
                cpa4(sa + db + soff + (unsigned)(u * 132 * 4), arow + kc + u);
                cpa4(sb + db + soff + (unsigned)(u * 132 * 4), brow + kc + u);
            }
            CP_COMMIT();
        }
        const float* Ab = As[ch & 1];
        const float* Bb = Bs[ch & 1];
#pragma unroll
        for (int kk = 0; kk < 16; kk++) {
            float4 x0 = *(const float4*)&Ab[kk * 132 + ty * 8];
            float4 x1 = *(const float4*)&Ab[kk * 132 + ty * 8 + 4];
            float4 y0 = *(const float4*)&Bb[kk * 132 + tx * 8];
            float4 y1 = *(const float4*)&Bb[kk * 132 + tx * 8 + 4];
            float av[8] = {x0.x, x0.y, x0.z, x0.w, x1.x, x1.y, x1.z, x1.w};
            float bv[8] = {y0.x, y0.y, y0.z, y0.w, y1.x, y1.y, y1.z, y1.w};
#pragma unroll
            for (int i = 0; i < 8; i++)
#pragma unroll
                for (int j = 0; j < 8; j++) acc[i][j] += av[i] * bv[j];
        }
        __syncthreads();
    }
    float4 c0 = *(const float4*)&wab[n0 + tx * 8];
    float4 c1 = *(const float4*)&wab[n0 + tx * 8 + 4];
    float bb[8] = {c0.x, c0.y, c0.z, c0.w, c1.x, c1.y, c1.z, c1.w};
    float cs[8] = {};
#pragma unroll
    for (int i = 0; i < 8; i++)
#pragma unroll
        for (int j = 0; j < 8; j++) cs[j] += ftanh(acc[i][j] + bb[j]);
#pragma unroll
    for (int j = 0; j < 8; j++) As[0][ty * 128 + tx * 8 + j] = cs[j];
    __syncthreads();
    if (tid < 128) {
        float v = 0.f;
#pragma unroll
        for (int q = 0; q < 16; q++) v += As[0][q * 128 + tid];
        g_sentsumm[mt * 512 + n0 + tid] = v;   // m-tile == sentence mt
    }
}

// ---------------- K4: sentence gi[d][s][n] = sent_summ @ sWi[d]^T + sbi[d] ----------------
__global__ void __launch_bounds__(256) k_sgi(const float* __restrict__ sWi,
                                             const float* __restrict__ sbi) {
    int n0 = blockIdx.x * 64, d = blockIdx.y;
    __shared__ float As[32 * 68];
    __shared__ float Bs[32 * 68];
    int tid = threadIdx.x, tx = tid & 15, ty = tid >> 4;
    float acc[4][4] = {};
    for (int kc = 0; kc < 512; kc += 32) {
        for (int e = tid; e < 2048; e += 256) {
            int row = e >> 5, kk = e & 31;
            As[kk * 68 + row] = g_sentsumm[row * 512 + kc + kk];
            Bs[kk * 68 + row] = sWi[(d * 1536 + n0 + row) * 512 + kc + kk];
        }
        __syncthreads();
#pragma unroll
        for (int kk = 0; kk < 32; kk++) {
            float4 a = *(const float4*)&As[kk * 68 + ty * 4];
            float4 b = *(const float4*)&Bs[kk * 68 + tx * 4];
            float av[4] = {a.x, a.y, a.z, a.w};
            float bv[4] = {b.x, b.y, b.z, b.w};
#pragma unroll
            for (int i = 0; i < 4; i++)
#pragma unroll
                for (int j = 0; j < 4; j++) acc[i][j] += av[i] * bv[j];
        }
        __syncthreads();
    }
    float4 bbv = *(const float4*)&sbi[d * 1536 + n0 + tx * 4];
    float bvv[4] = {bbv.x, bbv.y, bbv.z, bbv.w};
#pragma unroll
    for (int i = 0; i < 4; i++) {
        int s = ty * 4 + i;
        float4 v = make_float4(acc[i][0] + bvv[0], acc[i][1] + bvv[1],
                               acc[i][2] + bvv[2], acc[i][3] + bvv[3]);
        *(float4*)&g_gis[(d * SS + s) * 1536 + n0 + tx * 4] = v;
    }
}

// ---------------- K5: sentence GRU-cell gates (zero state) ----------------
__global__ void k_sgates(const float* __restrict__ sbh) {
    int idx = blockIdx.x * blockDim.x + threadIdx.x;   // 65536
    int d = idx >> 15, r = idx & 32767, s = r >> 9, j = r & 511;
    const float* gi = g_gis + (d * SS + s) * 1536;
    float hr = sbh[d * 1536 + j], hz = sbh[d * 1536 + 512 + j], hn = sbh[d * 1536 + 1024 + j];
    float rr = fsig(gi[j] + hr);
    float z = fsig(gi[j + 512] + hz);
    float n = ftanh(gi[j + 1024] + rr * hn);
    g_sentenc[s * 1024 + d * 512 + j] = (1.0f - z) * n;
}

// ---------------- K6: u_sent = tanh(sentenc @ saW^T + sab) ----------------
__global__ void __launch_bounds__(256) k_usent(const float* __restrict__ saW,
                                               const float* __restrict__ sab) {
    int n0 = blockIdx.x * 64;
    __shared__ float As[32 * 68];
    __shared__ float Bs[32 * 68];
    int tid = threadIdx.x, tx = tid & 15, ty = tid >> 4;
    float acc[4][4] = {};
    for (int kc = 0; kc < 1024; kc += 32) {
        for (int e = tid; e < 2048; e += 256) {
            int row = e >> 5, kk = e & 31;
            As[kk * 68 + row] = g_sentenc[row * 1024 + kc + kk];
            Bs[kk * 68 + row] = saW[(n0 + row) * 1024 + kc + kk];
        }
        __syncthreads();
#pragma unroll
        for (int kk = 0; kk < 32; kk++) {
            float4 a = *(const float4*)&As[kk * 68 + ty * 4];
            float4 b = *(const float4*)&Bs[kk * 68 + tx * 4];
            float av[4] = {a.x, a.y, a.z, a.w};
            float bv[4] = {b.x, b.y, b.z, b.w};
#pragma unroll
            for (int i = 0; i < 4; i++)
#pragma unroll
                for (int j = 0; j < 4; j++) acc[i][j] += av[i] * bv[j];
        }
        __syncthreads();
    }
    float4 bbv = *(const float4*)&sab[n0 + tx * 4];
    float bvv[4] = {bbv.x, bbv.y, bbv.z, bbv.w};
#pragma unroll
    for (int i = 0; i < 4; i++) {
        int s = ty * 4 + i;
#pragma unroll
        for (int j = 0; j < 4; j++)
            g_usent[s * 1024 + n0 + tx * 4 + j] = ftanh(acc[i][j] + bvv[j]);
    }
}

// ---------------- K7: doc sum + logits + log_softmax (fused) ----------------
__global__ void k_final(const float* __restrict__ doW, const float* __restrict__ dob,
                        float* __restrict__ out) {
    __shared__ float doc_sm[1024];
    __shared__ float lg[16];
    int tid = threadIdx.x;
    for (int n = tid; n < 1024; n += 256) {
        float v = 0.f;
#pragma unroll 8
        for (int s = 0; s < SS; s++) v += g_usent[s * 1024 + n];
        doc_sm[n] = v;
    }
    __syncthreads();
    int warp = tid >> 5, lane = tid & 31;
    for (int c = warp; c < NC; c += 8) {
        float v = 0.f;
        for (int n = lane; n < 1024; n += 32) v += doc_sm[n] * doW[c * 1024 + n];
#pragma unroll
        for (int o = 16; o; o >>= 1) v += __shfl_xor_sync(0xffffffff, v, o);
        if (lane == 0) lg[c] = v + dob[c];
    }
    __syncthreads();
    if (tid == 0) {
        float mx = -1e30f;
        for (int c = 0; c < NC; c++) mx = fmaxf(mx, lg[c]);
        float se = 0.f;
        for (int c = 0; c < NC; c++) se += expf(lg[c] - mx);
        float lse = mx + logf(se);
        for (int c = 0; c < NC; c++) out[8256 + c] = lg[c] - lse;
    }
}

extern "C" void kernel_launch(void* const* d_in, const int* in_sizes, int n_in,
                              void* d_out, int out_size) {
    const int*   doc = (const int*)d_in[0];
    const float* emb = (const float*)d_in[1];
    const float* wWi = (const float*)d_in[2];
    const float* wWh = (const float*)d_in[3];
    const float* wbi = (const float*)d_in[4];
    const float* wbh = (const float*)d_in[5];
    const float* sWi = (const float*)d_in[6];
    const float* sbi = (const float*)d_in[8];
    const float* sbh = (const float*)d_in[9];
    const float* waW = (const float*)d_in[10];
    const float* wab = (const float*)d_in[11];
    const float* saW = (const float*)d_in[13];
    const float* sab = (const float*)d_in[14];
    const float* doW = (const float*)d_in[16];
    const float* dob = (const float*)d_in[17];
    float* out = (float*)d_out;

    k_init<<<64, 256>>>(out);
    k_gi<<<dim3(6, 64, 2), 256>>>(doc, emb, wWi, wbi);
    k_recur<<<128, 256>>>(wWh, wbh);
    k_uword<<<dim3(4, 64), 256>>>(waW, wab);    // profiled slot (index 3)
    k_sgi<<<dim3(24, 2), 256>>>(sWi, sbi);
    k_sgates<<<256, 256>>>(sbh);
    k_usent<<<16, 256>>>(saW, sab);
    k_final<<<1, 256>>>(doW, dob, out);
}

// round 15
// speedup vs baseline: 1.1640x; 1.1640x over previous
#include <cuda_runtime.h>
#include <math.h>

#define SS 64
#define WW 128
#define DD 256
#define HWW 256
#define NC 13

// ---------------- scratch ----------------
__device__ float g_gi[2 * WW * SS * 768];      // [d][w][s][768]
__device__ float g_wordenc[SS * WW * 512];     // [s*128+w][512]
__device__ float g_sentsumm[SS * 512];         // [s][512]
__device__ float g_gis[2 * SS * 1536];         // [d][s][1536]
__device__ float g_sentenc[SS * 1024];         // [s][1024]
__device__ float g_usent[SS * 1024];           // [s][1024]
__device__ float g_sink;

__device__ __forceinline__ float fsig(float x) {
    return __fdividef(1.0f, 1.0f + __expf(-x));
}
__device__ __forceinline__ float ftanh(float x) {
    return 1.0f - __fdividef(2.0f, __expf(2.0f * x) + 1.0f);
}

__device__ __forceinline__ unsigned long long ffma2(unsigned long long a,
                                                    unsigned long long b,
                                                    unsigned long long c) {
    unsigned long long d;
    asm("fma.rn.f32x2 %0, %1, %2, %3;" : "=l"(d) : "l"(a), "l"(b), "l"(c));
    return d;
}

__device__ __forceinline__ unsigned smem_u32(const void* p) {
    unsigned a;
    asm("{ .reg .u64 t; cvta.to.shared.u64 t, %1; cvt.u32.u64 %0, t; }" : "=r"(a) : "l"(p));
    return a;
}

// cluster-scope acquire wait on mbarrier phase parity
__device__ __forceinline__ void mbar_wait_cluster(unsigned mbar, unsigned parity) {
    asm volatile(
        "{\n\t.reg .pred P1;\n\t"
        "WAIT_LOOP_%=:\n\t"
        "mbarrier.try_wait.parity.acquire.cluster.shared::cta.b64 P1, [%0], %1, 0x989680;\n\t"
        "@P1 bra.uni WAIT_DONE_%=;\n\t"
        "bra.uni WAIT_LOOP_%=;\n\t"
        "WAIT_DONE_%=:\n\t}"
        :: "r"(mbar), "r"(parity) : "memory");
}

// ---------------- init ----------------
__global__ void k_init(float* __restrict__ out) {
    int i = blockIdx.x * blockDim.x + threadIdx.x;
    if (i < 8256) out[i] = 1.0f;   // word_w + sent_w are softmax over size-1 axis -> ones
}

// ---------------- K1: gi[d][m][n] = emb[doc[m]] @ wWi[d]^T + wbi[d],  m = w*64+s -------
// 128x128 tile, 8x8/thread. Double-buffered smem + float4 LDG prefetch:
// one __syncthreads per chunk, STS overlaps compute of the other buffer.
__global__ void __launch_bounds__(256) k_gi(const int* __restrict__ doc,
                                            const float* __restrict__ emb,
                                            const float* __restrict__ wWi,
                                            const float* __restrict__ wbi) {
    int n0 = blockIdx.x * 128, mt = blockIdx.y, d = blockIdx.z;
    __shared__ float As[2][16 * 132];
    __shared__ float Bs[2][16 * 132];
    __shared__ int toks[128];
    int tid = threadIdx.x;
    if (tid < 128) {
        int m = mt * 128 + tid;                  // w = m>>6, s = m&63
        toks[tid] = doc[(m & 63) * WW + (m >> 6)];
    }
    __syncthreads();
    int tx = tid & 15, ty = tid >> 4;
    int lrow = tid >> 1, kk0 = (tid & 1) * 8;
    const float* arow = emb + (long)toks[lrow] * DD + kk0;
    const float* brow = wWi + (d * 768 + n0 + lrow) * 256 + kk0;

    // chunk 0 -> buf 0
    {
        float4 a0 = *(const float4*)(arow);
        float4 a1 = *(const float4*)(arow + 4);
        float4 b0 = *(const float4*)(brow);
        float4 b1 = *(const float4*)(brow + 4);
        float am[8] = {a0.x, a0.y, a0.z, a0.w, a1.x, a1.y, a1.z, a1.w};
        float bm[8] = {b0.x, b0.y, b0.z, b0.w, b1.x, b1.y, b1.z, b1.w};
#pragma unroll
        for (int u = 0; u < 8; u++) {
            As[0][(kk0 + u) * 132 + lrow] = am[u];
            Bs[0][(kk0 + u) * 132 + lrow] = bm[u];
        }
    }
    __syncthreads();

    float acc[8][8] = {};
    for (int ch = 0; ch < 16; ch++) {
        float4 a0, a1, b0, b1;
        bool more = (ch + 1 < 16);
        if (more) {                              // LDG for next chunk, hidden under FFMA
            int kc = (ch + 1) * 16;
            a0 = *(const float4*)(arow + kc);
            a1 = *(const float4*)(arow + kc + 4);
            b0 = *(const float4*)(brow + kc);
            b1 = *(const float4*)(brow + kc + 4);
        }
        const float* Ab = As[ch & 1];
        const float* Bb = Bs[ch & 1];
#pragma unroll
        for (int kk = 0; kk < 16; kk++) {
            float4 x0 = *(const float4*)&Ab[kk * 132 + ty * 8];
            float4 x1 = *(const float4*)&Ab[kk * 132 + ty * 8 + 4];
            float4 y0 = *(const float4*)&Bb[kk * 132 + tx * 8];
            float4 y1 = *(const float4*)&Bb[kk * 132 + tx * 8 + 4];
            float av[8] = {x0.x, x0.y, x0.z, x0.w, x1.x, x1.y, x1.z, x1.w};
            float bv[8] = {y0.x, y0.y, y0.z, y0.w, y1.x, y1.y, y1.z, y1.w};
#pragma unroll
            for (int i = 0; i < 8; i++)
#pragma unroll
                for (int j = 0; j < 8; j++) acc[i][j] += av[i] * bv[j];
        }
        if (more) {                              // STS into the other buffer (disjoint)
            int nb = (ch + 1) & 1;
            float am[8] = {a0.x, a0.y, a0.z, a0.w, a1.x, a1.y, a1.z, a1.w};
            float bm[8] = {b0.x, b0.y, b0.z, b0.w, b1.x, b1.y, b1.z, b1.w};
#pragma unroll
            for (int u = 0; u < 8; u++) {
                As[nb][(kk0 + u) * 132 + lrow] = am[u];
                Bs[nb][(kk0 + u) * 132 + lrow] = bm[u];
            }
        }
        __syncthreads();
    }
    float4 c0 = *(const float4*)&wbi[d * 768 + n0 + tx * 8];
    float4 c1 = *(const float4*)&wbi[d * 768 + n0 + tx * 8 + 4];
    float bb[8] = {c0.x, c0.y, c0.z, c0.w, c1.x, c1.y, c1.z, c1.w};
#pragma unroll
    for (int i = 0; i < 8; i++) {
        int m = mt * 128 + ty * 8 + i;
        float* dst = g_gi + ((long)d * 8192 + m) * 768 + n0 + tx * 8;
        float4 v0 = make_float4(acc[i][0] + bb[0], acc[i][1] + bb[1],
                                acc[i][2] + bb[2], acc[i][3] + bb[3]);
        float4 v1 = make_float4(acc[i][4] + bb[4], acc[i][5] + bb[5],
                                acc[i][6] + bb[6], acc[i][7] + bb[7]);
        *(float4*)dst = v0;
        *(float4*)(dst + 4) = v1;
    }
}

// ---------------- K2: persistent word-GRU recurrence (unchanged from R13, passing) -------
__global__ void __launch_bounds__(256, 1) __cluster_dims__(8, 1, 1)
k_recur(const float* __restrict__ wWh, const float* __restrict__ wbh) {
    __shared__ __align__(16) float h_sm[2][2][4 * 264];     // [group][buf][4 rows]
    __shared__ __align__(8) unsigned long long mbars[2][2]; // [group][buf]
    int c = blockIdx.x;
    int d = c >> 6, sb = (c >> 3) & 7, jb = c & 7;
    int tid = threadIdx.x;
    int warp = tid >> 5, lane = tid & 31;
    int jq = lane >> 3, ks = lane & 7;
    int ks3 = ks & 3, hs = ks >> 2;
    int jg = jb * 32 + warp * 4 + jq;
    int sb8 = sb * 8;
    int kbase = ks3 * 64 + hs * 4;

    unsigned long long whr2[3][16];
#pragma unroll
    for (int g = 0; g < 3; g++) {
        const float* wr = wWh + (d * 768 + g * 256 + jg) * 256;
#pragma unroll
        for (int t = 0; t < 8; t++) {
            whr2[g][2 * t]     = *(const unsigned long long*)(wr + kbase + 8 * t);
            whr2[g][2 * t + 1] = *(const unsigned long long*)(wr + kbase + 8 * t + 2);
        }
    }
    float bhr = wbh[d * 768 + jg];
    float bhz = wbh[d * 768 + 256 + jg];
    float bhn = wbh[d * 768 + 512 + jg];

    for (int i = tid; i < 4 * 264; i += 256) {
        h_sm[0][0][i] = 0.0f;
        h_sm[1][0][i] = 0.0f;
    }
    int hoff[4];
#pragma unroll
    for (int i = 0; i < 4; i++) hoff[i] = (i ^ ks3) * 264;

    unsigned hbase = smem_u32(&h_sm[0][0][0]);
    unsigned mbase = smem_u32(&mbars[0][0]);
    unsigned dmb = mbase - hbase;
    unsigned pa[8];
#pragma unroll
    for (int r = 0; r < 8; r++) {
        unsigned peer;
        asm("mapa.shared::cluster.u32 %0, %1, %2;" : "=r"(peer) : "r"(hbase), "r"(r));
        pa[r] = peer;
    }

    if (tid == 0) {
#pragma unroll
        for (int g = 0; g < 2; g++)
#pragma unroll
            for (int b = 0; b < 2; b++)
                asm volatile("mbarrier.init.shared.b64 [%0], 1;"
                             :: "r"(mbase + (unsigned)((g * 2 + b) * 8)) : "memory");
    }
    asm volatile("barrier.cluster.arrive.aligned;" ::: "memory");
    asm volatile("barrier.cluster.wait.aligned;" ::: "memory");

    const float* gib = g_gi + ((d * WW) * SS + (sb8 + ks)) * 768 + jg;
    float gi0 = __ldg(gib), gi1 = __ldg(gib + 256), gi2 = __ldg(gib + 512);

    for (int w = 0; w < WW; w++) {
        int b = w & 1, bn = b ^ 1;
        unsigned parity = ((unsigned)(w >> 1) + 1u - (unsigned)b) & 1u;

        if (tid == 0 && w + 1 < WW) {
            asm volatile("mbarrier.arrive.expect_tx.shared::cta.b64 _, [%0], %1;"
                         :: "r"(mbase + (unsigned)(bn * 8)), "r"(4096u) : "memory");
            asm volatile("mbarrier.arrive.expect_tx.shared::cta.b64 _, [%0], %1;"
                         :: "r"(mbase + (unsigned)((2 + bn) * 8)), "r"(4096u) : "memory");
        }

#pragma unroll
        for (int g = 0; g < 2; g++) {
            if (w > 0) mbar_wait_cluster(mbase + (unsigned)((g * 2 + b) * 8), parity);
            const float* hp = &h_sm[g][b][0];

            unsigned long long acc2[3][4];
#pragma unroll
            for (int gg = 0; gg < 3; gg++)
#pragma unroll
                for (int i = 0; i < 4; i++) acc2[gg][i] = 0ull;
#pragma unroll
            for (int t = 0; t < 8; t++) {
#pragma unroll
                for (int i = 0; i < 4; i++) {
                    ulonglong2 hv = *(const ulonglong2*)(hp + hoff[i] + kbase + 8 * t);
#pragma unroll
                    for (int gg = 0; gg < 3; gg++) {
                        acc2[gg][i] = ffma2(hv.x, whr2[gg][2 * t], acc2[gg][i]);
                        acc2[gg][i] = ffma2(hv.y, whr2[gg][2 * t + 1], acc2[gg][i]);
                    }
                }
            }
            float a0[4], a1[4], a2[4];
#pragma unroll
            for (int i = 0; i < 4; i++) {
                float2 f0 = *(float2*)&acc2[0][i]; a0[i] = f0.x + f0.y;
                float2 f1 = *(float2*)&acc2[1][i]; a1[i] = f1.x + f1.y;
                float2 f2 = *(float2*)&acc2[2][i]; a2[i] = f2.x + f2.y;
            }
#pragma unroll
            for (int i = 0; i < 4; i++) {
                a0[i] += __shfl_xor_sync(0xffffffffu, a0[i], 4, 8);
                a1[i] += __shfl_xor_sync(0xffffffffu, a1[i], 4, 8);
                a2[i] += __shfl_xor_sync(0xffffffffu, a2[i], 4, 8);
            }
#pragma unroll
            for (int i = 0; i < 2; i++) {
                a0[i] += __shfl_xor_sync(0xffffffffu, a0[i ^ 2], 2, 8);
                a1[i] += __shfl_xor_sync(0xffffffffu, a1[i ^ 2], 2, 8);
                a2[i] += __shfl_xor_sync(0xffffffffu, a2[i ^ 2], 2, 8);
            }
            a0[0] += __shfl_xor_sync(0xffffffffu, a0[1], 1, 8);
            a1[0] += __shfl_xor_sync(0xffffffffu, a1[1], 1, 8);
            a2[0] += __shfl_xor_sync(0xffffffffu, a2[1], 1, 8);

            if (hs == g) {
                float h_old = hp[ks3 * 264 + jg];
                float r = fsig(gi0 + a0[0] + bhr);
                float z = fsig(gi1 + a1[0] + bhz);
                float n = ftanh(gi2 + r * (a2[0] + bhn));
                float hn = (1.0f - z) * n + z * h_old;

                if (w + 1 < WW) {
                    unsigned off = (unsigned)(((g * 2 + bn) * (4 * 264) + ks3 * 264 + jg) * 4);
                    unsigned mboff = dmb + (unsigned)((g * 2 + bn) * 8);
                    unsigned uv = __float_as_uint(hn);
#pragma unroll
                    for (int r8 = 0; r8 < 8; r8++) {
                        asm volatile(
                            "st.async.shared::cluster.mbarrier::complete_tx::bytes.b32 [%0], %1, [%2];"
                            :: "r"(pa[r8] + off), "r"(uv), "r"(pa[r8] + mboff) : "memory");
                    }
                }
                g_wordenc[((sb8 + ks) * WW + w) * 512 + d * 256 + jg] = hn;
                if (w + 1 < WW) {
                    const float* gn = gib + (w + 1) * (SS * 768);
                    gi0 = __ldg(gn); gi1 = __ldg(gn + 256); gi2 = __ldg(gn + 512);
                }
            }
        }
    }
    asm volatile("barrier.cluster.arrive.aligned;" ::: "memory");
    asm volatile("barrier.cluster.wait.aligned;" ::: "memory");
}

// ---------------- K3: u_word GEMM + fused per-sentence reduction (double-buffered) -------
__global__ void __launch_bounds__(256) k_uword(const float* __restrict__ waW,
                                               const float* __restrict__ wab) {
    int n0 = blockIdx.x * 128, mt = blockIdx.y;
    __shared__ float As[2][16 * 132];
    __shared__ float Bs[2][16 * 132];
    int tid = threadIdx.x;
    int tx = tid & 15, ty = tid >> 4;
    int lrow = tid >> 1, kk0 = (tid & 1) * 8;
    const float* arow = g_wordenc + (mt * 128 + lrow) * 512 + kk0;
    const float* brow = waW + (n0 + lrow) * 512 + kk0;

    {
        float4 a0 = *(const float4*)(arow);
        float4 a1 = *(const float4*)(arow + 4);
        float4 b0 = *(const float4*)(brow);
        float4 b1 = *(const float4*)(brow + 4);
        float am[8] = {a0.x, a0.y, a0.z, a0.w, a1.x, a1.y, a1.z, a1.w};
        float bm[8] = {b0.x, b0.y, b0.z, b0.w, b1.x, b1.y, b1.z, b1.w};
#pragma unroll
        for (int u = 0; u < 8; u++) {
            As[0][(kk0 + u) * 132 + lrow] = am[u];
            Bs[0][(kk0 + u) * 132 + lrow] = bm[u];
        }
    }
    __syncthreads();

    float acc[8][8] = {};
    for (int ch = 0; ch < 32; ch++) {
        float4 a0, a1, b0, b1;
        bool more = (ch + 1 < 32);
        if (more) {
            int kc = (ch + 1) * 16;
            a0 = *(const float4*)(arow + kc);
            a1 = *(const float4*)(arow + kc + 4);
            b0 = *(const float4*)(brow + kc);
            b1 = *(const float4*)(brow + kc + 4);
        }
        const float* Ab = As[ch & 1];
        const float* Bb = Bs[ch & 1];
#pragma unroll
        for (int kk = 0; kk < 16; kk++) {
            float4 x0 = *(const float4*)&Ab[kk * 132 + ty * 8];
            float4 x1 = *(const float4*)&Ab[kk * 132 + ty * 8 + 4];
            float4 y0 = *(const float4*)&Bb[kk * 132 + tx * 8];
            float4 y1 = *(const float4*)&Bb[kk * 132 + tx * 8 + 4];
            float av[8] = {x0.x, x0.y, x0.z, x0.w, x1.x, x1.y, x1.z, x1.w};
            float bv[8] = {y0.x, y0.y, y0.z, y0.w, y1.x, y1.y, y1.z, y1.w};
#pragma unroll
            for (int i = 0; i < 8; i++)
#pragma unroll
                for (int j = 0; j < 8; j++) acc[i][j] += av[i] * bv[j];
        }
        if (more) {
            int nb = (ch + 1) & 1;
            float am[8] = {a0.x, a0.y, a0.z, a0.w, a1.x, a1.y, a1.z, a1.w};
            float bm[8] = {b0.x, b0.y, b0.z, b0.w, b1.x, b1.y, b1.z, b1.w};
#pragma unroll
            for (int u = 0; u < 8; u++) {
                As[nb][(kk0 + u) * 132 + lrow] = am[u];
                Bs[nb][(kk0 + u) * 132 + lrow] = bm[u];
            }
        }
        __syncthreads();
    }
    float4 c0 = *(const float4*)&wab[n0 + tx * 8];
    float4 c1 = *(const float4*)&wab[n0 + tx * 8 + 4];
    float bb[8] = {c0.x, c0.y, c0.z, c0.w, c1.x, c1.y, c1.z, c1.w};
    float cs[8] = {};
#pragma unroll
    for (int i = 0; i < 8; i++)
#pragma unroll
        for (int j = 0; j < 8; j++) cs[j] += ftanh(acc[i][j] + bb[j]);
#pragma unroll
    for (int j = 0; j < 8; j++) As[0][ty * 128 + tx * 8 + j] = cs[j];
    __syncthreads();
    if (tid < 128) {
        float v = 0.f;
#pragma unroll
        for (int q = 0; q < 16; q++) v += As[0][q * 128 + tid];
        g_sentsumm[mt * 512 + n0 + tid] = v;   // m-tile == sentence mt
    }
}

// ---------------- K4: sentence gi[d][s][n] = sent_summ @ sWi[d]^T + sbi[d] ----------------
__global__ void __launch_bounds__(256) k_sgi(const float* __restrict__ sWi,
                                             const float* __restrict__ sbi) {
    int n0 = blockIdx.x * 64, d = blockIdx.y;
    __shared__ float As[32 * 68];
    __shared__ float Bs[32 * 68];
    int tid = threadIdx.x, tx = tid & 15, ty = tid >> 4;
    float acc[4][4] = {};
    for (int kc = 0; kc < 512; kc += 32) {
        for (int e = tid; e < 2048; e += 256) {
            int row = e >> 5, kk = e & 31;
            As[kk * 68 + row] = g_sentsumm[row * 512 + kc + kk];
            Bs[kk * 68 + row] = sWi[(d * 1536 + n0 + row) * 512 + kc + kk];
        }
        __syncthreads();
#pragma unroll
        for (int kk = 0; kk < 32; kk++) {
            float4 a = *(const float4*)&As[kk * 68 + ty * 4];
            float4 b = *(const float4*)&Bs[kk * 68 + tx * 4];
            float av[4] = {a.x, a.y, a.z, a.w};
            float bv[4] = {b.x, b.y, b.z, b.w};
#pragma unroll
            for (int i = 0; i < 4; i++)
#pragma unroll
                for (int j = 0; j < 4; j++) acc[i][j] += av[i] * bv[j];
        }
        __syncthreads();
    }
    float4 bbv = *(const float4*)&sbi[d * 1536 + n0 + tx * 4];
    float bvv[4] = {bbv.x, bbv.y, bbv.z, bbv.w};
#pragma unroll
    for (int i = 0; i < 4; i++) {
        int s = ty * 4 + i;
        float4 v = make_float4(acc[i][0] + bvv[0], acc[i][1] + bvv[1],
                               acc[i][2] + bvv[2], acc[i][3] + bvv[3]);
        *(float4*)&g_gis[(d * SS + s) * 1536 + n0 + tx * 4] = v;
    }
}

// ---------------- K5: sentence GRU-cell gates (zero state) ----------------
__global__ void k_sgates(const float* __restrict__ sbh) {
    int idx = blockIdx.x * blockDim.x + threadIdx.x;   // 65536
    int d = idx >> 15, r = idx & 32767, s = r >> 9, j = r & 511;
    const float* gi = g_gis + (d * SS + s) * 1536;
    float hr = sbh[d * 1536 + j], hz = sbh[d * 1536 + 512 + j], hn = sbh[d * 1536 + 1024 + j];
    float rr = fsig(gi[j] + hr);
    float z = fsig(gi[j + 512] + hz);
    float n = ftanh(gi[j + 1024] + rr * hn);
    g_sentenc[s * 1024 + d * 512 + j] = (1.0f - z) * n;
}

// ---------------- K6: u_sent = tanh(sentenc @ saW^T + sab) ----------------
__global__ void __launch_bounds__(256) k_usent(const float* __restrict__ saW,
                                               const float* __restrict__ sab) {
    int n0 = blockIdx.x * 64;
    __shared__ float As[32 * 68];
    __shared__ float Bs[32 * 68];
    int tid = threadIdx.x, tx = tid & 15, ty = tid >> 4;
    float acc[4][4] = {};
    for (int kc = 0; kc < 1024; kc += 32) {
        for (int e = tid; e < 2048; e += 256) {
            int row = e >> 5, kk = e & 31;
            As[kk * 68 + row] = g_sentenc[row * 1024 + kc + kk];
            Bs[kk * 68 + row] = saW[(n0 + row) * 1024 + kc + kk];
        }
        __syncthreads();
#pragma unroll
        for (int kk = 0; kk < 32; kk++) {
            float4 a = *(const float4*)&As[kk * 68 + ty * 4];
            float4 b = *(const float4*)&Bs[kk * 68 + tx * 4];
            float av[4] = {a.x, a.y, a.z, a.w};
            float bv[4] = {b.x, b.y, b.z, b.w};
#pragma unroll
            for (int i = 0; i < 4; i++)
#pragma unroll
                for (int j = 0; j < 4; j++) acc[i][j] += av[i] * bv[j];
        }
        __syncthreads();
    }
    float4 bbv = *(const float4*)&sab[n0 + tx * 4];
    float bvv[4] = {bbv.x, bbv.y, bbv.z, bbv.w};
#pragma unroll
    for (int i = 0; i < 4; i++) {
        int s = ty * 4 + i;
#pragma unroll
        for (int j = 0; j < 4; j++)
            g_usent[s * 1024 + n0 + tx * 4 + j] = ftanh(acc[i][j] + bvv[j]);
    }
}

// ---------------- K7: doc sum + logits + log_softmax (fused) ----------------
__global__ void k_final(const float* __restrict__ doW, const float* __restrict__ dob,
                        float* __restrict__ out) {
    __shared__ float doc_sm[1024];
    __shared__ float lg[16];
    int tid = threadIdx.x;
    for (int n = tid; n < 1024; n += 256) {
        float v = 0.f;
#pragma unroll 8
        for (int s = 0; s < SS; s++) v += g_usent[s * 1024 + n];
        doc_sm[n] = v;
    }
    __syncthreads();
    int warp = tid >> 5, lane = tid & 31;
    for (int c = warp; c < NC; c += 8) {
        float v = 0.f;
        for (int n = lane; n < 1024; n += 32) v += doc_sm[n] * doW[c * 1024 + n];
#pragma unroll
        for (int o = 16; o; o >>= 1) v += __shfl_xor_sync(0xffffffff, v, o);
        if (lane == 0) lg[c] = v + dob[c];
    }
    __syncthreads();
    if (tid == 0) {
        float mx = -1e30f;
        for (int c = 0; c < NC; c++) mx = fmaxf(mx, lg[c]);
        float se = 0.f;
        for (int c = 0; c < NC; c++) se += expf(lg[c] - mx);
        float lse = mx + logf(se);
        for (int c = 0; c < NC; c++) out[8256 + c] = lg[c] - lse;
    }
}

extern "C" void kernel_launch(void* const* d_in, const int* in_sizes, int n_in,
                              void* d_out, int out_size) {
    const int*   doc = (const int*)d_in[0];
    const float* emb = (const float*)d_in[1];
    const float* wWi = (const float*)d_in[2];
    const float* wWh = (const float*)d_in[3];
    const float* wbi = (const float*)d_in[4];
    const float* wbh = (const float*)d_in[5];
    const float* sWi = (const float*)d_in[6];
    const float* sbi = (const float*)d_in[8];
    const float* sbh = (const float*)d_in[9];
    const float* waW = (const float*)d_in[10];
    const float* wab = (const float*)d_in[11];
    const float* saW = (const float*)d_in[13];
    const float* sab = (const float*)d_in[14];
    const float* doW = (const float*)d_in[16];
    const float* dob = (const float*)d_in[17];
    float* out = (float*)d_out;

    k_init<<<64, 256>>>(out);
    k_gi<<<dim3(6, 64, 2), 256>>>(doc, emb, wWi, wbi);
    k_recur<<<128, 256>>>(wWh, wbh);
    k_uword<<<dim3(4, 64), 256>>>(waW, wab);    // profiled slot
    k_sgi<<<dim3(24, 2), 256>>>(sWi, sbi);
    k_sgates<<<256, 256>>>(sbh);
    k_usent<<<16, 256>>>(saW, sab);
    k_final<<<1, 256>>>(doW, dob, out);
}

// round 16
// speedup vs baseline: 1.2616x; 1.0838x over previous
#include <cuda_runtime.h>
#include <math.h>

#define SS 64
#define WW 128
#define DD 256
#define HWW 256
#define NC 13

// ---------------- scratch ----------------
__device__ float g_gi[2 * WW * SS * 768];      // [d][w][s][768]
__device__ float g_wordenc[SS * WW * 512];     // [s*128+w][512]
__device__ float g_sentsumm[SS * 512];         // [s][512]
__device__ float g_gis[2 * SS * 1536];         // [d][s][1536]
__device__ float g_sentenc[SS * 1024];         // [s][1024]
__device__ float g_usent[SS * 1024];           // [s][1024]
__device__ float g_sink;

__device__ __forceinline__ float fsig(float x) {
    return __fdividef(1.0f, 1.0f + __expf(-x));
}
__device__ __forceinline__ float ftanh(float x) {
    return 1.0f - __fdividef(2.0f, __expf(2.0f * x) + 1.0f);
}

__device__ __forceinline__ unsigned long long ffma2(unsigned long long a,
                                                    unsigned long long b,
                                                    unsigned long long c) {
    unsigned long long d;
    asm("fma.rn.f32x2 %0, %1, %2, %3;" : "=l"(d) : "l"(a), "l"(b), "l"(c));
    return d;
}

__device__ __forceinline__ unsigned smem_u32(const void* p) {
    unsigned a;
    asm("{ .reg .u64 t; cvta.to.shared.u64 t, %1; cvt.u32.u64 %0, t; }" : "=r"(a) : "l"(p));
    return a;
}

// cluster-scope acquire wait on mbarrier phase parity
__device__ __forceinline__ void mbar_wait_cluster(unsigned mbar, unsigned parity) {
    asm volatile(
        "{\n\t.reg .pred P1;\n\t"
        "WAIT_LOOP_%=:\n\t"
        "mbarrier.try_wait.parity.acquire.cluster.shared::cta.b64 P1, [%0], %1, 0x989680;\n\t"
        "@P1 bra.uni WAIT_DONE_%=;\n\t"
        "bra.uni WAIT_LOOP_%=;\n\t"
        "WAIT_DONE_%=:\n\t}"
        :: "r"(mbar), "r"(parity) : "memory");
}

// ---------------- init ----------------
__global__ void k_init(float* __restrict__ out) {
    int i = blockIdx.x * blockDim.x + threadIdx.x;
    if (i < 8256) out[i] = 1.0f;   // word_w + sent_w are softmax over size-1 axis -> ones
}

// ---------------- K1: gi[d][m][n] = emb[doc[m]] @ wWi[d]^T + wbi[d],  m = w*64+s -------
// 128x128 tile, 8x8/thread, double-buffered smem + float4 LDG prefetch (R15, passing).
__global__ void __launch_bounds__(256) k_gi(const int* __restrict__ doc,
                                            const float* __restrict__ emb,
                                            const float* __restrict__ wWi,
                                            const float* __restrict__ wbi) {
    int n0 = blockIdx.x * 128, mt = blockIdx.y, d = blockIdx.z;
    __shared__ float As[2][16 * 132];
    __shared__ float Bs[2][16 * 132];
    __shared__ int toks[128];
    int tid = threadIdx.x;
    if (tid < 128) {
        int m = mt * 128 + tid;                  // w = m>>6, s = m&63
        toks[tid] = doc[(m & 63) * WW + (m >> 6)];
    }
    __syncthreads();
    int tx = tid & 15, ty = tid >> 4;
    int lrow = tid >> 1, kk0 = (tid & 1) * 8;
    const float* arow = emb + (long)toks[lrow] * DD + kk0;
    const float* brow = wWi + (d * 768 + n0 + lrow) * 256 + kk0;

    {
        float4 a0 = *(const float4*)(arow);
        float4 a1 = *(const float4*)(arow + 4);
        float4 b0 = *(const float4*)(brow);
        float4 b1 = *(const float4*)(brow + 4);
        float am[8] = {a0.x, a0.y, a0.z, a0.w, a1.x, a1.y, a1.z, a1.w};
        float bm[8] = {b0.x, b0.y, b0.z, b0.w, b1.x, b1.y, b1.z, b1.w};
#pragma unroll
        for (int u = 0; u < 8; u++) {
            As[0][(kk0 + u) * 132 + lrow] = am[u];
            Bs[0][(kk0 + u) * 132 + lrow] = bm[u];
        }
    }
    __syncthreads();

    float acc[8][8] = {};
    for (int ch = 0; ch < 16; ch++) {
        float4 a0, a1, b0, b1;
        bool more = (ch + 1 < 16);
        if (more) {
            int kc = (ch + 1) * 16;
            a0 = *(const float4*)(arow + kc);
            a1 = *(const float4*)(arow + kc + 4);
            b0 = *(const float4*)(brow + kc);
            b1 = *(const float4*)(brow + kc + 4);
        }
        const float* Ab = As[ch & 1];
        const float* Bb = Bs[ch & 1];
#pragma unroll
        for (int kk = 0; kk < 16; kk++) {
            float4 x0 = *(const float4*)&Ab[kk * 132 + ty * 8];
            float4 x1 = *(const float4*)&Ab[kk * 132 + ty * 8 + 4];
            float4 y0 = *(const float4*)&Bb[kk * 132 + tx * 8];
            float4 y1 = *(const float4*)&Bb[kk * 132 + tx * 8 + 4];
            float av[8] = {x0.x, x0.y, x0.z, x0.w, x1.x, x1.y, x1.z, x1.w};
            float bv[8] = {y0.x, y0.y, y0.z, y0.w, y1.x, y1.y, y1.z, y1.w};
#pragma unroll
            for (int i = 0; i < 8; i++)
#pragma unroll
                for (int j = 0; j < 8; j++) acc[i][j] += av[i] * bv[j];
        }
        if (more) {
            int nb = (ch + 1) & 1;
            float am[8] = {a0.x, a0.y, a0.z, a0.w, a1.x, a1.y, a1.z, a1.w};
            float bm[8] = {b0.x, b0.y, b0.z, b0.w, b1.x, b1.y, b1.z, b1.w};
#pragma unroll
            for (int u = 0; u < 8; u++) {
                As[nb][(kk0 + u) * 132 + lrow] = am[u];
                Bs[nb][(kk0 + u) * 132 + lrow] = bm[u];
            }
        }
        __syncthreads();
    }
    float4 c0 = *(const float4*)&wbi[d * 768 + n0 + tx * 8];
    float4 c1 = *(const float4*)&wbi[d * 768 + n0 + tx * 8 + 4];
    float bb[8] = {c0.x, c0.y, c0.z, c0.w, c1.x, c1.y, c1.z, c1.w};
#pragma unroll
    for (int i = 0; i < 8; i++) {
        int m = mt * 128 + ty * 8 + i;
        float* dst = g_gi + ((long)d * 8192 + m) * 768 + n0 + tx * 8;
        float4 v0 = make_float4(acc[i][0] + bb[0], acc[i][1] + bb[1],
                                acc[i][2] + bb[2], acc[i][3] + bb[3]);
        float4 v1 = make_float4(acc[i][4] + bb[4], acc[i][5] + bb[5],
                                acc[i][6] + bb[6], acc[i][7] + bb[7]);
        *(float4*)dst = v0;
        *(float4*)(dst + 4) = v1;
    }
}

// ---------------- K2: persistent word-GRU recurrence (broadcast layout) ------------------
// 128 CTAs = 16 clusters of 8 (jb splits of one (d,sb)); CTA covers 32 j, 8 sentences
// in two independent 4-row groups A (s0-3) / B (s4-7), R13 mbarrier/st.async protocol.
// NEW compute layout: lane = local j (jg = jb*32+lane), warp q = k-slice [32q, 32q+32).
// All h loads are warp-UNIFORM 16B -> broadcast, 1 wavefront each (was 4): LDS volume
// drops 2048 -> ~512 wavefront-cycles/step. k-reduction across the 8 warps via a small
// smem matrix; warps 0-3 own rows 0-3 of both groups (gates + st.async + wordenc).
__global__ void __launch_bounds__(256, 1) __cluster_dims__(8, 1, 1)
k_recur(const float* __restrict__ wWh, const float* __restrict__ wbh) {
    __shared__ __align__(16) float h_sm[2][2][1024];        // [group][buf][4 rows x 256 j]
    __shared__ float red_sm[8][12][33];                     // [kslice][gate*4+row][j]
    __shared__ __align__(8) unsigned long long mbars[2][2]; // [group][buf]
    int c = blockIdx.x;
    int d = c >> 6, sb = (c >> 3) & 7, jb = c & 7;
    int tid = threadIdx.x;
    int q = tid >> 5, lane = tid & 31;     // q = k-slice, lane = local j
    int jg = jb * 32 + lane;
    int sb8 = sb * 8;
    bool owner = (q < 4);                  // warp q<4 owns row r=q of both groups

    // weights for k in [q*32, q*32+32), rows (g, jg): 48 ull = 96 floats
    unsigned long long whr2[3][16];
#pragma unroll
    for (int g = 0; g < 3; g++) {
        const unsigned long long* wr = (const unsigned long long*)
            (wWh + (d * 768 + g * 256 + jg) * 256 + q * 32);
#pragma unroll
        for (int t = 0; t < 16; t++) whr2[g][t] = wr[t];
    }
    float bhr = wbh[d * 768 + jg];
    float bhz = wbh[d * 768 + 256 + jg];
    float bhn = wbh[d * 768 + 512 + jg];

    // zero buffer 0 of both groups (h0 = 0)
    for (int i = tid; i < 1024; i += 256) {
        h_sm[0][0][i] = 0.0f;
        h_sm[1][0][i] = 0.0f;
    }

    unsigned hbase = smem_u32(&h_sm[0][0][0]);
    unsigned mbase = smem_u32(&mbars[0][0]);
    unsigned dmb = mbase - hbase;
    unsigned pa[8];
#pragma unroll
    for (int r8 = 0; r8 < 8; r8++) {
        unsigned peer;
        asm("mapa.shared::cluster.u32 %0, %1, %2;" : "=r"(peer) : "r"(hbase), "r"(r8));
        pa[r8] = peer;
    }
    if (tid == 0) {
#pragma unroll
        for (int g = 0; g < 2; g++)
#pragma unroll
            for (int b = 0; b < 2; b++)
                asm volatile("mbarrier.init.shared.b64 [%0], 1;"
                             :: "r"(mbase + (unsigned)((g * 2 + b) * 8)) : "memory");
    }
    asm volatile("barrier.cluster.arrive.aligned;" ::: "memory");
    asm volatile("barrier.cluster.wait.aligned;" ::: "memory");

    // owner gi pointers: group A sentence sb8+q, group B sentence sb8+4+q
    const float* giP[2];
    giP[0] = g_gi + ((long)(d * WW) * SS + (sb8 + q)) * 768 + jg;
    giP[1] = g_gi + ((long)(d * WW) * SS + (sb8 + 4 + q)) * 768 + jg;
    float gir[2][3];
    if (owner) {
#pragma unroll
        for (int g = 0; g < 2; g++) {
            gir[g][0] = __ldg(giP[g]);
            gir[g][1] = __ldg(giP[g] + 256);
            gir[g][2] = __ldg(giP[g] + 512);
        }
    }

    for (int w = 0; w < WW; w++) {
        int b = w & 1, bn = b ^ 1;
        unsigned parity = ((unsigned)(w >> 1) + 1u - (unsigned)b) & 1u;

        if (tid == 0 && w + 1 < WW) {
            asm volatile("mbarrier.arrive.expect_tx.shared::cta.b64 _, [%0], %1;"
                         :: "r"(mbase + (unsigned)(bn * 8)), "r"(4096u) : "memory");
            asm volatile("mbarrier.arrive.expect_tx.shared::cta.b64 _, [%0], %1;"
                         :: "r"(mbase + (unsigned)((2 + bn) * 8)), "r"(4096u) : "memory");
        }

#pragma unroll
        for (int g = 0; g < 2; g++) {
            if (w > 0) mbar_wait_cluster(mbase + (unsigned)((g * 2 + b) * 8), parity);
            const float* hp = &h_sm[g][b][0];

            // phase A: partials over k-slice q for all 4 rows (uniform 16B loads)
            unsigned long long acc2[3][4];
#pragma unroll
            for (int gg = 0; gg < 3; gg++)
#pragma unroll
                for (int rr = 0; rr < 4; rr++) acc2[gg][rr] = 0ull;
#pragma unroll
            for (int rr = 0; rr < 4; rr++) {
#pragma unroll
                for (int t = 0; t < 8; t++) {
                    ulonglong2 hv = *(const ulonglong2*)(hp + rr * 256 + q * 32 + t * 4);
#pragma unroll
                    for (int gg = 0; gg < 3; gg++) {
                        acc2[gg][rr] = ffma2(hv.x, whr2[gg][2 * t], acc2[gg][rr]);
                        acc2[gg][rr] = ffma2(hv.y, whr2[gg][2 * t + 1], acc2[gg][rr]);
                    }
                }
            }
#pragma unroll
            for (int gg = 0; gg < 3; gg++)
#pragma unroll
                for (int rr = 0; rr < 4; rr++) {
                    float2 f = *(float2*)&acc2[gg][rr];
                    red_sm[q][gg * 4 + rr][lane] = f.x + f.y;
                }
            __syncthreads();

            // phase B: owner warps reduce 8 k-slices, gates, send
            if (owner) {
                float gh[3];
#pragma unroll
                for (int gg = 0; gg < 3; gg++) {
                    float v = 0.f;
#pragma unroll
                    for (int qq = 0; qq < 8; qq++) v += red_sm[qq][gg * 4 + q][lane];
                    gh[gg] = v;
                }
                float h_old = hp[q * 256 + jg];
                float r = fsig(gir[g][0] + gh[0] + bhr);
                float z = fsig(gir[g][1] + gh[1] + bhz);
                float n = ftanh(gir[g][2] + r * (gh[2] + bhn));
                float hn = (1.0f - z) * n + z * h_old;

                if (w + 1 < WW) {
                    unsigned off = (unsigned)(((g * 2 + bn) * 1024 + q * 256 + jg) * 4);
                    unsigned mboff = dmb + (unsigned)((g * 2 + bn) * 8);
                    unsigned uv = __float_as_uint(hn);
#pragma unroll
                    for (int r8 = 0; r8 < 8; r8++) {
                        asm volatile(
                            "st.async.shared::cluster.mbarrier::complete_tx::bytes.b32 [%0], %1, [%2];"
                            :: "r"(pa[r8] + off), "r"(uv), "r"(pa[r8] + mboff) : "memory");
                    }
                }
                g_wordenc[((sb8 + g * 4 + q) * WW + w) * 512 + d * 256 + jg] = hn;
                if (w + 1 < WW) {
                    const float* gn = giP[g] + (long)(w + 1) * (SS * 768);
                    gir[g][0] = __ldg(gn);
                    gir[g][1] = __ldg(gn + 256);
                    gir[g][2] = __ldg(gn + 512);
                }
            }
            __syncthreads();   // red_sm safe for next group / next step
        }
    }
    asm volatile("barrier.cluster.arrive.aligned;" ::: "memory");
    asm volatile("barrier.cluster.wait.aligned;" ::: "memory");
}

// ---------------- K3: u_word GEMM + fused per-sentence reduction (double-buffered) -------
__global__ void __launch_bounds__(256) k_uword(const float* __restrict__ waW,
                                               const float* __restrict__ wab) {
    int n0 = blockIdx.x * 128, mt = blockIdx.y;
    __shared__ float As[2][16 * 132];
    __shared__ float Bs[2][16 * 132];
    int tid = threadIdx.x;
    int tx = tid & 15, ty = tid >> 4;
    int lrow = tid >> 1, kk0 = (tid & 1) * 8;
    const float* arow = g_wordenc + (mt * 128 + lrow) * 512 + kk0;
    const float* brow = waW + (n0 + lrow) * 512 + kk0;

    {
        float4 a0 = *(const float4*)(arow);
        float4 a1 = *(const float4*)(arow + 4);
        float4 b0 = *(const float4*)(brow);
        float4 b1 = *(const float4*)(brow + 4);
        float am[8] = {a0.x, a0.y, a0.z, a0.w, a1.x, a1.y, a1.z, a1.w};
        float bm[8] = {b0.x, b0.y, b0.z, b0.w, b1.x, b1.y, b1.z, b1.w};
#pragma unroll
        for (int u = 0; u < 8; u++) {
            As[0][(kk0 + u) * 132 + lrow] = am[u];
            Bs[0][(kk0 + u) * 132 + lrow] = bm[u];
        }
    }
    __syncthreads();

    float acc[8][8] = {};
    for (int ch = 0; ch < 32; ch++) {
        float4 a0, a1, b0, b1;
        bool more = (ch + 1 < 32);
        if (more) {
            int kc = (ch + 1) * 16;
            a0 = *(const float4*)(arow + kc);
            a1 = *(const float4*)(arow + kc + 4);
            b0 = *(const float4*)(brow + kc);
            b1 = *(const float4*)(brow + kc + 4);
        }
        const float* Ab = As[ch & 1];
        const float* Bb = Bs[ch & 1];
#pragma unroll
        for (int kk = 0; kk < 16; kk++) {
            float4 x0 = *(const float4*)&Ab[kk * 132 + ty * 8];
            float4 x1 = *(const float4*)&Ab[kk * 132 + ty * 8 + 4];
            float4 y0 = *(const float4*)&Bb[kk * 132 + tx * 8];
            float4 y1 = *(const float4*)&Bb[kk * 132 + tx * 8 + 4];
            float av[8] = {x0.x, x0.y, x0.z, x0.w, x1.x, x1.y, x1.z, x1.w};
            float bv[8] = {y0.x, y0.y, y0.z, y0.w, y1.x, y1.y, y1.z, y1.w};
#pragma unroll
            for (int i = 0; i < 8; i++)
#pragma unroll
                for (int j = 0; j < 8; j++) acc[i][j] += av[i] * bv[j];
        }
        if (more) {
            int nb = (ch + 1) & 1;
            float am[8] = {a0.x, a0.y, a0.z, a0.w, a1.x, a1.y, a1.z, a1.w};
            float bm[8] = {b0.x, b0.y, b0.z, b0.w, b1.x, b1.y, b1.z, b1.w};
#pragma unroll
            for (int u = 0; u < 8; u++) {
                As[nb][(kk0 + u) * 132 + lrow] = am[u];
                Bs[nb][(kk0 + u) * 132 + lrow] = bm[u];
            }
        }
        __syncthreads();
    }
    float4 c0 = *(const float4*)&wab[n0 + tx * 8];
    float4 c1 = *(const float4*)&wab[n0 + tx * 8 + 4];
    float bb[8] = {c0.x, c0.y, c0.z, c0.w, c1.x, c1.y, c1.z, c1.w};
    float cs[8] = {};
#pragma unroll
    for (int i = 0; i < 8; i++)
#pragma unroll
        for (int j = 0; j < 8; j++) cs[j] += ftanh(acc[i][j] + bb[j]);
#pragma unroll
    for (int j = 0; j < 8; j++) As[0][ty * 128 + tx * 8 + j] = cs[j];
    __syncthreads();
    if (tid < 128) {
        float v = 0.f;
#pragma unroll
        for (int q = 0; q < 16; q++) v += As[0][q * 128 + tid];
        g_sentsumm[mt * 512 + n0 + tid] = v;   // m-tile == sentence mt
    }
}

// ---------------- K4: sentence gi[d][s][n] = sent_summ @ sWi[d]^T + sbi[d] ----------------
__global__ void __launch_bounds__(256) k_sgi(const float* __restrict__ sWi,
                                             const float* __restrict__ sbi) {
    int n0 = blockIdx.x * 64, d = blockIdx.y;
    __shared__ float As[32 * 68];
    __shared__ float Bs[32 * 68];
    int tid = threadIdx.x, tx = tid & 15, ty = tid >> 4;
    float acc[4][4] = {};
    for (int kc = 0; kc < 512; kc += 32) {
        for (int e = tid; e < 2048; e += 256) {
            int row = e >> 5, kk = e & 31;
            As[kk * 68 + row] = g_sentsumm[row * 512 + kc + kk];
            Bs[kk * 68 + row] = sWi[(d * 1536 + n0 + row) * 512 + kc + kk];
        }
        __syncthreads();
#pragma unroll
        for (int kk = 0; kk < 32; kk++) {
            float4 a = *(const float4*)&As[kk * 68 + ty * 4];
            float4 b = *(const float4*)&Bs[kk * 68 + tx * 4];
            float av[4] = {a.x, a.y, a.z, a.w};
            float bv[4] = {b.x, b.y, b.z, b.w};
#pragma unroll
            for (int i = 0; i < 4; i++)
#pragma unroll
                for (int j = 0; j < 4; j++) acc[i][j] += av[i] * bv[j];
        }
        __syncthreads();
    }
    float4 bbv = *(const float4*)&sbi[d * 1536 + n0 + tx * 4];
    float bvv[4] = {bbv.x, bbv.y, bbv.z, bbv.w};
#pragma unroll
    for (int i = 0; i < 4; i++) {
        int s = ty * 4 + i;
        float4 v = make_float4(acc[i][0] + bvv[0], acc[i][1] + bvv[1],
                               acc[i][2] + bvv[2], acc[i][3] + bvv[3]);
        *(float4*)&g_gis[(d * SS + s) * 1536 + n0 + tx * 4] = v;
    }
}

// ---------------- K5: sentence GRU-cell gates (zero state) ----------------
__global__ void k_sgates(const float* __restrict__ sbh) {
    int idx = blockIdx.x * blockDim.x + threadIdx.x;   // 65536
    int d = idx >> 15, r = idx & 32767, s = r >> 9, j = r & 511;
    const float* gi = g_gis + (d * SS + s) * 1536;
    float hr = sbh[d * 1536 + j], hz = sbh[d * 1536 + 512 + j], hn = sbh[d * 1536 + 1024 + j];
    float rr = fsig(gi[j] + hr);
    float z = fsig(gi[j + 512] + hz);
    float n = ftanh(gi[j + 1024] + rr * hn);
    g_sentenc[s * 1024 + d * 512 + j] = (1.0f - z) * n;
}

// ---------------- K6: u_sent = tanh(sentenc @ saW^T + sab) ----------------
__global__ void __launch_bounds__(256) k_usent(const float* __restrict__ saW,
                                               const float* __restrict__ sab) {
    int n0 = blockIdx.x * 64;
    __shared__ float As[32 * 68];
    __shared__ float Bs[32 * 68];
    int tid = threadIdx.x, tx = tid & 15, ty = tid >> 4;
    float acc[4][4] = {};
    for (int kc = 0; kc < 1024; kc += 32) {
        for (int e = tid; e < 2048; e += 256) {
            int row = e >> 5, kk = e & 31;
            As[kk * 68 + row] = g_sentenc[row * 1024 + kc + kk];
            Bs[kk * 68 + row] = saW[(n0 + row) * 1024 + kc + kk];
        }
        __syncthreads();
#pragma unroll
        for (int kk = 0; kk < 32; kk++) {
            float4 a = *(const float4*)&As[kk * 68 + ty * 4];
            float4 b = *(const float4*)&Bs[kk * 68 + tx * 4];
            float av[4] = {a.x, a.y, a.z, a.w};
            float bv[4] = {b.x, b.y, b.z, b.w};
#pragma unroll
            for (int i = 0; i < 4; i++)
#pragma unroll
                for (int j = 0; j < 4; j++) acc[i][j] += av[i] * bv[j];
        }
        __syncthreads();
    }
    float4 bbv = *(const float4*)&sab[n0 + tx * 4];
    float bvv[4] = {bbv.x, bbv.y, bbv.z, bbv.w};
#pragma unroll
    for (int i = 0; i < 4; i++) {
        int s = ty * 4 + i;
#pragma unroll
        for (int j = 0; j < 4; j++)
            g_usent[s * 1024 + n0 + tx * 4 + j] = ftanh(acc[i][j] + bvv[j]);
    }
}

// ---------------- K7: doc sum + logits + log_softmax (fused) ----------------
__global__ void k_final(const float* __restrict__ doW, const float* __restrict__ dob,
                        float* __restrict__ out) {
    __shared__ float doc_sm[1024];
    __shared__ float lg[16];
    int tid = threadIdx.x;
    for (int n = tid; n < 1024; n += 256) {
        float v = 0.f;
#pragma unroll 8
        for (int s = 0; s < SS; s++) v += g_usent[s * 1024 + n];
        doc_sm[n] = v;
    }
    __syncthreads();
    int warp = tid >> 5, lane = tid & 31;
    for (int c = warp; c < NC; c += 8) {
        float v = 0.f;
        for (int n = lane; n < 1024; n += 32) v += doc_sm[n] * doW[c * 1024 + n];
#pragma unroll
        for (int o = 16; o; o >>= 1) v += __shfl_xor_sync(0xffffffff, v, o);
        if (lane == 0) lg[c] = v + dob[c];
    }
    __syncthreads();
    if (tid == 0) {
        float mx = -1e30f;
        for (int c = 0; c < NC; c++) mx = fmaxf(mx, lg[c]);
        float se = 0.f;
        for (int c = 0; c < NC; c++) se += expf(lg[c] - mx);
        float lse = mx + logf(se);
        for (int c = 0; c < NC; c++) out[8256 + c] = lg[c] - lse;
    }
}

extern "C" void kernel_launch(void* const* d_in, const int* in_sizes, int n_in,
                              void* d_out, int out_size) {
    const int*   doc = (const int*)d_in[0];
    const float* emb = (const float*)d_in[1];
    const float* wWi = (const float*)d_in[2];
    const float* wWh = (const float*)d_in[3];
    const float* wbi = (const float*)d_in[4];
    const float* wbh = (const float*)d_in[5];
    const float* sWi = (const float*)d_in[6];
    const float* sbi = (const float*)d_in[8];
    const float* sbh = (const float*)d_in[9];
    const float* waW = (const float*)d_in[10];
    const float* wab = (const float*)d_in[11];
    const float* saW = (const float*)d_in[13];
    const float* sab = (const float*)d_in[14];
    const float* doW = (const float*)d_in[16];
    const float* dob = (const float*)d_in[17];
    float* out = (float*)d_out;

    k_init<<<64, 256>>>(out);
    k_gi<<<dim3(6, 64, 2), 256>>>(doc, emb, wWi, wbi);
    k_recur<<<128, 256>>>(wWh, wbh);
    k_uword<<<dim3(4, 64), 256>>>(waW, wab);    // profiled slot
    k_sgi<<<dim3(24, 2), 256>>>(sWi, sbi);
    k_sgates<<<256, 256>>>(sbh);
    k_usent<<<16, 256>>>(saW, sab);
    k_final<<<1, 256>>>(doW, dob, out);
}